// round 1
// baseline (speedup 1.0000x reference)
#include <cuda_runtime.h>
#include <cstdint>

// Problem constants (match reference)
#define BN 64
#define TN 1024
#define DN 256
#define KMAX 128
#define EPSF 1e-3f
#define LOG_PI_F 1.1447298858494002f

// ---------------------------------------------------------------------------
// Static device scratch (no allocations allowed in kernel_launch)
// ---------------------------------------------------------------------------
__device__ int   g_cnt [BN * KMAX];            // cluster sizes per (b,k)
__device__ int   g_list[BN * KMAX * TN];       // time indices per (b,k), ordered (32 MB)
__device__ float g_crp [BN * KMAX];            // CRP partial log-prob per (b,k)

// per-dim derived constants
__device__ float g_kappa0[DN], g_a[DN], g_b[DN], g_a0[DN], g_b0[DN];
__device__ float g_kl[DN], g_kll[DN];
__device__ float g_lgA0B0[DN], g_lgA0[DN], g_lgB0[DN], g_lgA[DN];

// ---------------------------------------------------------------------------
// Kernel 0: zero the output (it is poisoned by the harness)
// ---------------------------------------------------------------------------
__global__ void k_zero_out(float* out)
{
    int i = threadIdx.x;
    if (i < BN) out[i] = 0.0f;
}

// ---------------------------------------------------------------------------
// Kernel 1: per-dim constants (one thread per dim)
// ---------------------------------------------------------------------------
__global__ void k_setup_dims(const float* __restrict__ loc,
                             const float* __restrict__ log_mean_conc,
                             const float* __restrict__ log_conc,
                             const float* __restrict__ log_scale,
                             const float* __restrict__ sparse_prior_logit)
{
    int d = threadIdx.x;
    if (d >= DN) return;
    float kappa0 = expf(fminf(log_mean_conc[d], 12.0f));
    float a      = expf(log_conc[d]);        // NIG concentration
    float b      = expf(log_scale[d]);       // NIG scale
    float a0     = 2.0f * a + 4.0f;          // nu + 1, nu = 2a+3
    float b0     = a0 * expf(sparse_prior_logit[d]);
    float l      = loc[d];

    g_kappa0[d] = kappa0;
    g_a[d]      = a;
    g_b[d]      = b;
    g_a0[d]     = a0;
    g_b0[d]     = b0;
    g_kl[d]     = kappa0 * l;
    g_kll[d]    = kappa0 * l * l;
    g_lgA0B0[d] = lgammaf(a0 + b0);
    g_lgA0[d]   = lgammaf(a0);
    g_lgB0[d]   = lgammaf(b0);
    g_lgA[d]    = lgammaf(a);
}

// ---------------------------------------------------------------------------
// Kernel 2: build ordered per-(b,k) time lists + CRP partial sums.
// One thread per (b,k). Lanes of a warp share b, so z reads broadcast.
// CRP: at the j-th observation of cluster k at global time t:
//   crp = (j>0 ? log(j) : log(alpha)=0) - log(t + alpha), alpha = 1.
// ---------------------------------------------------------------------------
__global__ void k_build_lists(const int* __restrict__ z)
{
    int tid = blockIdx.x * blockDim.x + threadIdx.x;
    if (tid >= BN * KMAX) return;
    int b = tid >> 7;       // / KMAX
    int k = tid & (KMAX - 1);
    const int* zr = z + b * TN;
    int* lst = g_list + (size_t)tid * TN;

    int c = 0;
    float crp = 0.0f;
#pragma unroll 4
    for (int t = 0; t < TN; t++) {
        int zv = __ldg(zr + t);
        if (zv == k) {
            lst[c] = t;
            float num = (c > 0) ? __logf((float)c) : 0.0f;
            crp += num - __logf((float)t + 1.0f);
            c++;
        }
    }
    g_cnt[tid] = c;
    g_crp[tid] = crp;
}

// ---------------------------------------------------------------------------
// Kernel 3: main chain evaluation.
// Grid: (KMAX, BN) CTAs, 256 threads (one per dim).
// Per nonzero obs:  -y - 0.5*log(pi) + an*log(q) - (an+0.5)*log(q + dy^2)
//   with kn = kappa0+m1, mn = (kappa0*loc + ss1)/kn, an = a + m1/2,
//        bn = b + 0.5*(ss2 + kappa0*loc^2 - kn*mn^2), q = 2*bn*(kn+1)/kn.
// All counting/gammaln terms telescope to chain-end lgamma differences.
// ---------------------------------------------------------------------------
__global__ void __launch_bounds__(256)
k_main(const float* __restrict__ X, float* __restrict__ out)
{
    const int k = blockIdx.x;
    const int b = blockIdx.y;
    const int d = threadIdx.x;
    const int id = b * KMAX + k;

    const int cnt = g_cnt[id];
    float acc = 0.0f;

    if (cnt > 0) {
        const float kappa0 = g_kappa0[d];
        const float a      = g_a[d];
        const float bpr    = g_b[d];
        const float a0     = g_a0[d];
        const float b0     = g_b0[d];
        const float kl     = g_kl[d];
        const float kll    = g_kll[d];

        const int* lst = g_list + (size_t)id * TN;
        const float* Xb = X + ((size_t)b * TN) * DN + d;

        float m1f = 0.0f, ss1 = 0.0f, ss2 = 0.0f;

        // software-pipelined X prefetch
        int t0 = __ldg(lst);
        float x = __ldg(Xb + (size_t)t0 * DN);

        for (int j = 0; j < cnt; j++) {
            float xn = 0.0f;
            if (j + 1 < cnt) {
                int tn = __ldg(lst + j + 1);
                xn = __ldg(Xb + (size_t)tn * DN);
            }
            if (x > EPSF) {
                float y   = __logf(x);
                float kn  = kappa0 + m1f;
                float rkn = __fdividef(1.0f, kn);
                float mn  = (kl + ss1) * rkn;
                float an  = fmaf(0.5f, m1f, a);
                float bn  = fmaf(0.5f, ss2 + kll - kn * mn * mn, bpr);
                float q   = 2.0f * bn * (kn + 1.0f) * rkn;
                float dy  = y - mn;
                float Lq  = __logf(q);
                float Lqd = __logf(fmaf(dy, dy, q));
                // -y - 0.5*log(pi*q) - (an+0.5)*(log(q+dy^2)-log(q))
                acc += -y + an * Lq - (an + 0.5f) * Lqd;
                ss1 += y;
                ss2  = fmaf(y, y, ss2);
                m1f += 1.0f;
            }
            x = xn;
        }

        // telescoped chain-end terms
        const float cntf = (float)cnt;
        const float zf   = cntf - m1f;              // final zero count
        acc += -0.5f * LOG_PI_F * m1f;              // folded per-obs -0.5*log(pi)
        acc += (lgammaf(a0 + m1f)         - g_lgA0[d])     // Sum log(a0+m1)
             + (lgammaf(b0 + zf)          - g_lgB0[d])     // Sum log(b0+n0)
             + (lgammaf(fmaf(0.5f, m1f, a)) - g_lgA[d])    // Sum Delta (gammaln ratio)
             - (lgammaf(a0 + b0 + cntf)   - g_lgA0B0[d]);  // -Sum ldenom
    }

    if (d == 0) acc += g_crp[id];

    // block reduction
    __shared__ float red[256];
    red[d] = acc;
    __syncthreads();
#pragma unroll
    for (int s = 128; s > 0; s >>= 1) {
        if (d < s) red[d] += red[d + s];
        __syncthreads();
    }
    if (d == 0) atomicAdd(&out[b], -red[0]);
}

// ---------------------------------------------------------------------------
// Entry point. Input order: X, loc, log_mean_conc, log_conc, log_scale,
// sparse_prior_logit, z. Output: float[BN] (negative log-prob).
// ---------------------------------------------------------------------------
extern "C" void kernel_launch(void* const* d_in, const int* in_sizes, int n_in,
                              void* d_out, int out_size)
{
    const float* X   = (const float*)d_in[0];
    const float* loc = (const float*)d_in[1];
    const float* lmc = (const float*)d_in[2];
    const float* lc  = (const float*)d_in[3];
    const float* ls  = (const float*)d_in[4];
    const float* spl = (const float*)d_in[5];
    const int*   z   = (const int*)d_in[6];
    float* out = (float*)d_out;

    k_zero_out<<<1, 64>>>(out);
    k_setup_dims<<<1, 256>>>(loc, lmc, lc, ls, spl);
    k_build_lists<<<(BN * KMAX + 255) / 256, 256>>>(z);
    dim3 grid(KMAX, BN);
    k_main<<<grid, 256>>>(X, out);
}

// round 2
// speedup vs baseline: 1.9317x; 1.9317x over previous
#include <cuda_runtime.h>
#include <cstdint>

// Problem constants (match reference)
#define BN 64
#define TN 1024
#define DN 256
#define KMAX 128
#define EPSF 1e-3f
#define LOG_PI_F 1.1447298858494002f
#define MMAXT 64          // lgamma table depth (max cluster size covered)

// ---------------------------------------------------------------------------
// Static device scratch
// ---------------------------------------------------------------------------
__device__ int   g_cnt [BN * KMAX];            // cluster sizes per (b,k)
__device__ int   g_list[BN * KMAX * TN];       // time indices per (b,k), ordered

// per-dim derived constants (fallback path + loop constants)
__device__ float g_kappa0[DN], g_a[DN], g_b[DN], g_a0[DN], g_b0[DN];
__device__ float g_kl[DN], g_kll[DN];
__device__ float g_lgA0B0[DN], g_lgA0[DN], g_lgB0[DN], g_lgA[DN];

// lgamma difference tables: tab[m][d] = lgamma(const_d + step*m) - lgamma(const_d)
__device__ float g_tabA0[MMAXT * DN];   // a0 + m
__device__ float g_tabB0[MMAXT * DN];   // b0 + m
__device__ float g_tabAB[MMAXT * DN];   // a0 + b0 + m
__device__ float g_tabAh[MMAXT * DN];   // a  + 0.5*m

// ---------------------------------------------------------------------------
// Kernel 1: per-dim constants + lgamma tables + zero output.
// grid = MMAXT blocks (one per table row m), block = DN threads (one per dim).
// ---------------------------------------------------------------------------
__global__ void k_setup(const float* __restrict__ loc,
                        const float* __restrict__ log_mean_conc,
                        const float* __restrict__ log_conc,
                        const float* __restrict__ log_scale,
                        const float* __restrict__ sparse_prior_logit,
                        float* __restrict__ out)
{
    int m = blockIdx.x;
    int d = threadIdx.x;

    float kappa0 = expf(fminf(log_mean_conc[d], 12.0f));
    float a      = expf(log_conc[d]);
    float b      = expf(log_scale[d]);
    float a0     = 2.0f * a + 4.0f;                 // nu + 1, nu = 2a+3
    float b0     = a0 * expf(sparse_prior_logit[d]);
    float l      = loc[d];

    float lgA0   = lgammaf(a0);
    float lgB0   = lgammaf(b0);
    float lgAB   = lgammaf(a0 + b0);
    float lgA    = lgammaf(a);

    if (m == 0) {
        g_kappa0[d] = kappa0;
        g_a[d]      = a;
        g_b[d]      = b;
        g_a0[d]     = a0;
        g_b0[d]     = b0;
        g_kl[d]     = kappa0 * l;
        g_kll[d]    = kappa0 * l * l;
        g_lgA0[d]   = lgA0;
        g_lgB0[d]   = lgB0;
        g_lgA0B0[d] = lgAB;
        g_lgA[d]    = lgA;
        if (d < BN) out[d] = 0.0f;                  // out is poisoned by harness
    }

    float fm = (float)m;
    g_tabA0[m * DN + d] = lgammaf(a0 + fm)        - lgA0;
    g_tabB0[m * DN + d] = lgammaf(b0 + fm)        - lgB0;
    g_tabAB[m * DN + d] = lgammaf(a0 + b0 + fm)   - lgAB;
    g_tabAh[m * DN + d] = lgammaf(fmaf(0.5f, fm, a)) - lgA;
}

// ---------------------------------------------------------------------------
// Kernel 2: build ordered per-(b,k) time lists + counts.
// One WARP per batch row b. Stable within-chunk ranking via __match_any_sync.
// grid = BN/8 blocks of 256 threads (8 warps).
// ---------------------------------------------------------------------------
__global__ void __launch_bounds__(256) k_build(const int* __restrict__ z)
{
    __shared__ int cs[8][KMAX];
    const int wl   = threadIdx.x >> 5;
    const int lane = threadIdx.x & 31;
    const int b    = blockIdx.x * 8 + wl;

    for (int i = threadIdx.x; i < 8 * KMAX; i += blockDim.x)
        ((int*)cs)[i] = 0;
    __syncthreads();

    const int* zr = z + b * TN;
    int* cw = cs[wl];
    const unsigned lmlt = (1u << lane) - 1u;

    for (int t0 = 0; t0 < TN; t0 += 32) {
        int t  = t0 + lane;
        int zv = __ldg(zr + t);                         // coalesced
        unsigned mask = __match_any_sync(0xffffffffu, zv);
        int rank = __popc(mask & lmlt);                 // stable rank in chunk
        int base = cw[zv];                              // running count
        __syncwarp();
        g_list[((size_t)(b * KMAX + zv)) * TN + base + rank] = t;
        if (rank == 0)                                  // group leader bumps count
            cw[zv] = base + __popc(mask);
        __syncwarp();
    }

    for (int k = lane; k < KMAX; k += 32)
        g_cnt[b * KMAX + k] = cw[k];
}

// ---------------------------------------------------------------------------
// Kernel 3: main chain evaluation.
// Grid: (KMAX, BN) CTAs, 256 threads (one per dim).
// Per nonzero obs:  -y - 0.5*log(pi) + an*log(q) - (an+0.5)*log(q + dy^2)
// All counting/gammaln terms telescope to chain-end lgamma differences,
// fetched from precomputed tables (lgammaf fallback for cnt >= MMAXT).
// CRP: Sum_k lgamma(cnt_k) - lgamma(T+1) per batch row.
// ---------------------------------------------------------------------------
__global__ void __launch_bounds__(256)
k_main(const float* __restrict__ X, float* __restrict__ out)
{
    const int k  = blockIdx.x;
    const int b  = blockIdx.y;
    const int d  = threadIdx.x;
    const int id = b * KMAX + k;

    const int cnt = g_cnt[id];
    float acc = 0.0f;

    if (cnt > 0) {
        const float kappa0 = g_kappa0[d];
        const float a      = g_a[d];
        const float bpr    = g_b[d];
        const float kl     = g_kl[d];
        const float kll    = g_kll[d];

        const int* lst = g_list + (size_t)id * TN;
        const float* Xb = X + ((size_t)b * TN) * DN + d;

        float m1f = 0.0f, ss1 = 0.0f, ss2 = 0.0f;

        int t0 = __ldg(lst);
        float x = __ldg(Xb + (size_t)t0 * DN);

        for (int j = 0; j < cnt; j++) {
            float xn = 0.0f;
            if (j + 1 < cnt) {
                int tn = __ldg(lst + j + 1);
                xn = __ldg(Xb + (size_t)tn * DN);
            }
            if (x > EPSF) {
                float y   = __logf(x);
                float kn  = kappa0 + m1f;
                float rkn = __fdividef(1.0f, kn);
                float mn  = (kl + ss1) * rkn;
                float an  = fmaf(0.5f, m1f, a);
                float bn  = fmaf(0.5f, ss2 + kll - kn * mn * mn, bpr);
                float q   = 2.0f * bn * (kn + 1.0f) * rkn;
                float dy  = y - mn;
                float Lq  = __logf(q);
                float Lqd = __logf(fmaf(dy, dy, q));
                acc += -y + an * Lq - (an + 0.5f) * Lqd;
                ss1 += y;
                ss2  = fmaf(y, y, ss2);
                m1f += 1.0f;
            }
            x = xn;
        }

        const int   M1 = (int)m1f;
        const int   Z  = cnt - M1;
        acc += -0.5f * LOG_PI_F * m1f;
        if (cnt < MMAXT) {
            acc += g_tabA0[M1 * DN + d]      // Sum log(a0+m1)      (nonzero obs)
                 + g_tabB0[Z  * DN + d]      // Sum log(b0+n0)      (zero obs)
                 + g_tabAh[M1 * DN + d]      // Sum lgamma ratio    (Student-t)
                 - g_tabAB[cnt * DN + d];    // -Sum log(a0+b0+ck)  (all obs)
        } else {
            const float a0 = g_a0[d], b0 = g_b0[d];
            acc += (lgammaf(a0 + m1f)            - g_lgA0[d])
                 + (lgammaf(b0 + (float)Z)       - g_lgB0[d])
                 + (lgammaf(fmaf(0.5f, m1f, a))  - g_lgA[d])
                 - (lgammaf(a0 + b0 + (float)cnt) - g_lgA0B0[d]);
        }
    }

    // CRP (fully telescoped): Sum_k lgamma(cnt_k) - lgamma(T+1)
    if (d == 0) {
        if (cnt > 0) acc += lgammaf((float)cnt);
        if (k == 0)  acc -= lgammaf((float)(TN + 1));
    }

    // warp shuffle + cross-warp reduction
    const int lane = d & 31, wid = d >> 5;
#pragma unroll
    for (int o = 16; o; o >>= 1)
        acc += __shfl_down_sync(0xffffffffu, acc, o);
    __shared__ float wsum[8];
    if (lane == 0) wsum[wid] = acc;
    __syncthreads();
    if (d == 0) {
        float tot = 0.0f;
#pragma unroll
        for (int i = 0; i < 8; i++) tot += wsum[i];
        atomicAdd(&out[b], -tot);
    }
}

// ---------------------------------------------------------------------------
// Entry point. Inputs: X, loc, log_mean_conc, log_conc, log_scale,
// sparse_prior_logit, z. Output: float[BN].
// ---------------------------------------------------------------------------
extern "C" void kernel_launch(void* const* d_in, const int* in_sizes, int n_in,
                              void* d_out, int out_size)
{
    const float* X   = (const float*)d_in[0];
    const float* loc = (const float*)d_in[1];
    const float* lmc = (const float*)d_in[2];
    const float* lc  = (const float*)d_in[3];
    const float* ls  = (const float*)d_in[4];
    const float* spl = (const float*)d_in[5];
    const int*   z   = (const int*)d_in[6];
    float* out = (float*)d_out;

    k_setup<<<MMAXT, DN>>>(loc, lmc, lc, ls, spl, out);
    k_build<<<BN / 8, 256>>>(z);
    dim3 grid(KMAX, BN);
    k_main<<<grid, 256>>>(X, out);
}

// round 4
// speedup vs baseline: 2.1400x; 1.1079x over previous
#include <cuda_runtime.h>
#include <cstdint>

// Problem constants (match reference)
#define BN 64
#define TN 1024
#define DN 256
#define KMAX 128
#define EPSF 1e-3f
#define LOG_PI_F 1.1447298858494002f
#define MMAXT 64                       // lgamma table depth
#define HALF_L2PI 0.91893853320467274f // 0.5*log(2*pi)

// ---------------------------------------------------------------------------
// Static device scratch
// ---------------------------------------------------------------------------
__device__ int   g_cnt [BN * KMAX];
__device__ int   g_list[BN * KMAX * TN];

// per-dim constants (16B-aligned for float4 loads in k_main)
__device__ __align__(16) float g_kappa0[DN];
__device__ __align__(16) float g_a[DN];
__device__ __align__(16) float g_b[DN];
__device__ __align__(16) float g_kl[DN];
__device__ __align__(16) float g_kll[DN];
__device__ float g_a0[DN], g_b0[DN];
__device__ float g_lgA0B0[DN], g_lgA0[DN], g_lgB0[DN], g_lgA[DN];

// lgamma difference tables: tab[m][d] = lg(const_d + step*m) - lg(const_d)
__device__ float g_tabA0[MMAXT * DN];
__device__ float g_tabB0[MMAXT * DN];
__device__ float g_tabAB[MMAXT * DN];
__device__ float g_tabAh[MMAXT * DN];

// ---------------------------------------------------------------------------
// Fast lgamma for x > 0: shift to x>=8 (unrolled, predicated), then Stirling.
// Abs error < ~1e-5; tables store *differences* of this routine so systematic
// parts cancel.
// ---------------------------------------------------------------------------
__device__ __forceinline__ float fast_lgamma(float x)
{
    float prod = 1.0f;
#pragma unroll
    for (int i = 0; i < 8; i++) {
        if (x < 8.0f) { prod *= x; x += 1.0f; }
    }
    float rx  = __frcp_rn(x);
    float rx2 = rx * rx;
    float ser = rx * (8.33333333e-2f + rx2 * (-2.77777778e-3f + rx2 * 7.93650794e-4f));
    float lx  = __logf(x);
    return fmaf(x - 0.5f, lx, -x) + HALF_L2PI + ser - __logf(prod);
}

// ---------------------------------------------------------------------------
// Kernel 1 (fused prep): blocks [0, MMAXT) build lgamma tables + constants;
// blocks [MMAXT, MMAXT+8) build per-(b,k) time lists (one warp per batch row).
// ---------------------------------------------------------------------------
__global__ void __launch_bounds__(256)
k_prep(const float* __restrict__ loc,
       const float* __restrict__ log_mean_conc,
       const float* __restrict__ log_conc,
       const float* __restrict__ log_scale,
       const float* __restrict__ sparse_prior_logit,
       const int*   __restrict__ z,
       float* __restrict__ out)
{
    if (blockIdx.x < MMAXT) {
        // ---- table row m = blockIdx.x, dim d = threadIdx.x ----
        const int m = blockIdx.x;
        const int d = threadIdx.x;
        float kappa0 = expf(fminf(log_mean_conc[d], 12.0f));
        float a      = expf(log_conc[d]);
        float b      = expf(log_scale[d]);
        float a0     = 2.0f * a + 4.0f;                 // nu+1, nu = 2a+3
        float b0     = a0 * expf(sparse_prior_logit[d]);
        float l      = loc[d];

        float lgA0 = fast_lgamma(a0);
        float lgB0 = fast_lgamma(b0);
        float lgAB = fast_lgamma(a0 + b0);
        float lgA  = fast_lgamma(a);

        if (m == 0) {
            g_kappa0[d] = kappa0;
            g_a[d]      = a;
            g_b[d]      = b;
            g_a0[d]     = a0;
            g_b0[d]     = b0;
            g_kl[d]     = kappa0 * l;
            g_kll[d]    = kappa0 * l * l;
            // exact bases for the (rare) cnt>=MMAXT fallback path
            g_lgA0[d]   = lgammaf(a0);
            g_lgB0[d]   = lgammaf(b0);
            g_lgA0B0[d] = lgammaf(a0 + b0);
            g_lgA[d]    = lgammaf(a);
            if (d < BN) out[d] = 0.0f;                  // out is poisoned
        }

        float fm = (float)m;
        g_tabA0[m * DN + d] = fast_lgamma(a0 + fm)          - lgA0;
        g_tabB0[m * DN + d] = fast_lgamma(b0 + fm)          - lgB0;
        g_tabAB[m * DN + d] = fast_lgamma(a0 + b0 + fm)     - lgAB;
        g_tabAh[m * DN + d] = fast_lgamma(fmaf(0.5f, fm, a)) - lgA;
    } else {
        // ---- list build: one warp per batch row ----
        __shared__ int cs[8][KMAX];
        const int wl   = threadIdx.x >> 5;
        const int lane = threadIdx.x & 31;
        const int b    = (blockIdx.x - MMAXT) * 8 + wl;

        for (int i = threadIdx.x; i < 8 * KMAX; i += blockDim.x)
            ((int*)cs)[i] = 0;
        __syncthreads();

        const int* zr = z + b * TN;
        int* cw = cs[wl];
        const unsigned lmlt = (1u << lane) - 1u;

        for (int t0 = 0; t0 < TN; t0 += 32) {
            int t  = t0 + lane;
            int zv = __ldg(zr + t);                          // coalesced
            unsigned mask = __match_any_sync(0xffffffffu, zv);
            int rank = __popc(mask & lmlt);                  // stable in-chunk rank
            int base = cw[zv];
            __syncwarp();
            g_list[((size_t)(b * KMAX + zv)) * TN + base + rank] = t;
            if (rank == 0)
                cw[zv] = base + __popc(mask);
            __syncwarp();
        }

        for (int k = lane; k < KMAX; k += 32)
            g_cnt[b * KMAX + k] = cw[k];
    }
}

// ---------------------------------------------------------------------------
// Per-observation update for one dim (nonzero hurdle branch).
// Student-t log-kernel with the gammaln ratio telescoped out:
//   an*log(q) - (an+0.5)*log(q + dy^2), q = 2*bn*(kn+1)/kn
// (-y and -0.5*log(pi) folded into the tail via ss1 and m1.)
// ---------------------------------------------------------------------------
__device__ __forceinline__ void obs_update(float x, float kappa0, float a, float bpr,
                                           float kl, float kll,
                                           float& m1, float& s1, float& s2, float& acc)
{
    if (x > EPSF) {
        float y   = __logf(x);
        float kn  = kappa0 + m1;
        float rkn = __fdividef(1.0f, kn);
        float mn  = (kl + s1) * rkn;
        float an  = fmaf(0.5f, m1, a);
        float bn  = fmaf(0.5f, s2 + kll - kn * mn * mn, bpr);
        float q   = 2.0f * bn * (kn + 1.0f) * rkn;
        float dy  = y - mn;
        acc += an * __logf(q) - (an + 0.5f) * __logf(fmaf(dy, dy, q));
        s1 += y;
        s2  = fmaf(y, y, s2);
        m1 += 1.0f;
    }
}

// Chain-end telescoped terms for one dim.
__device__ __forceinline__ float tail_term(int d, int cnt, float m1, float s1, float a)
{
    const int M1 = (int)m1;
    const int Z  = cnt - M1;
    float r = fmaf(-0.5f * LOG_PI_F, m1, -s1);   // folded -0.5*log(pi) and -Sum y
    if (cnt < MMAXT) {
        r += g_tabA0[M1 * DN + d]      // Sum log(a0+m1)       (nonzero obs)
           + g_tabB0[Z  * DN + d]      // Sum log(b0+n0)       (zero obs)
           + g_tabAh[M1 * DN + d]      // Sum lgamma ratio     (Student-t)
           - g_tabAB[cnt * DN + d];    // -Sum log(a0+b0+ck)
    } else {
        float a0 = g_a0[d], b0 = g_b0[d];
        r += (lgammaf(a0 + m1)             - g_lgA0[d])
           + (lgammaf(b0 + (float)Z)       - g_lgB0[d])
           + (lgammaf(fmaf(0.5f, m1, a))   - g_lgA[d])
           - (lgammaf(a0 + b0 + (float)cnt) - g_lgA0B0[d]);
    }
    return r;
}

// ---------------------------------------------------------------------------
// Kernel 2: main chain evaluation.
// Grid (BN, KMAX), 64 threads; each thread owns 4 consecutive dims and the
// CTA streams its cluster's X rows as coalesced float4 (full 1KB row / iter).
// ---------------------------------------------------------------------------
__global__ void __launch_bounds__(64)
k_main(const float* __restrict__ X, float* __restrict__ out)
{
    const int b  = blockIdx.x;
    const int k  = blockIdx.y;
    const int t  = threadIdx.x;       // 0..63, dims 4t..4t+3
    const int id = b * KMAX + k;

    const int cnt = g_cnt[id];
    float acc = 0.0f;

    if (cnt > 0) {
        const float4 K   = ((const float4*)g_kappa0)[t];
        const float4 A   = ((const float4*)g_a)[t];
        const float4 Bp  = ((const float4*)g_b)[t];
        const float4 KL  = ((const float4*)g_kl)[t];
        const float4 KLL = ((const float4*)g_kll)[t];

        const int* lst = g_list + (size_t)id * TN;
        const float4* Xb = (const float4*)X + ((size_t)b * TN) * (DN / 4) + t;

        float m1a = 0.f, s1a = 0.f, s2a = 0.f;
        float m1b = 0.f, s1b = 0.f, s2b = 0.f;
        float m1c = 0.f, s1c = 0.f, s2c = 0.f;
        float m1d = 0.f, s1d = 0.f, s2d = 0.f;

        int tj = __ldg(lst);
        float4 x = __ldg(Xb + (size_t)tj * (DN / 4));

        for (int j = 0; j < cnt; j++) {
            float4 xn = make_float4(0.f, 0.f, 0.f, 0.f);
            if (j + 1 < cnt) {
                int tn = __ldg(lst + j + 1);
                xn = __ldg(Xb + (size_t)tn * (DN / 4));
            }
            obs_update(x.x, K.x, A.x, Bp.x, KL.x, KLL.x, m1a, s1a, s2a, acc);
            obs_update(x.y, K.y, A.y, Bp.y, KL.y, KLL.y, m1b, s1b, s2b, acc);
            obs_update(x.z, K.z, A.z, Bp.z, KL.z, KLL.z, m1c, s1c, s2c, acc);
            obs_update(x.w, K.w, A.w, Bp.w, KL.w, KLL.w, m1d, s1d, s2d, acc);
            x = xn;
        }

        const int d0 = t * 4;
        acc += tail_term(d0 + 0, cnt, m1a, s1a, A.x);
        acc += tail_term(d0 + 1, cnt, m1b, s1b, A.y);
        acc += tail_term(d0 + 2, cnt, m1c, s1c, A.z);
        acc += tail_term(d0 + 3, cnt, m1d, s1d, A.w);
    }

    // CRP (fully telescoped): Sum_k lgamma(cnt_k) - lgamma(T+1) per batch row
    if (t == 0) {
        if (cnt > 0) acc += fast_lgamma((float)cnt);
        if (k == 0)  acc -= lgammaf((float)(TN + 1));
    }

    // 2-warp reduction
    const int lane = t & 31, wid = t >> 5;
#pragma unroll
    for (int o = 16; o; o >>= 1)
        acc += __shfl_down_sync(0xffffffffu, acc, o);
    __shared__ float wsum[2];
    if (lane == 0) wsum[wid] = acc;
    __syncthreads();
    if (t == 0)
        atomicAdd(&out[b], -(wsum[0] + wsum[1]));
}

// ---------------------------------------------------------------------------
// Entry point. Inputs: X, loc, log_mean_conc, log_conc, log_scale,
// sparse_prior_logit, z. Output: float[BN].
// ---------------------------------------------------------------------------
extern "C" void kernel_launch(void* const* d_in, const int* in_sizes, int n_in,
                              void* d_out, int out_size)
{
    const float* X   = (const float*)d_in[0];
    const float* loc = (const float*)d_in[1];
    const float* lmc = (const float*)d_in[2];
    const float* lc  = (const float*)d_in[3];
    const float* ls  = (const float*)d_in[4];
    const float* spl = (const float*)d_in[5];
    const int*   z   = (const int*)d_in[6];
    float* out = (float*)d_out;

    k_prep<<<MMAXT + BN / 8, 256>>>(loc, lmc, lc, ls, spl, z, out);
    dim3 grid(BN, KMAX);
    k_main<<<grid, 64>>>(X, out);
}

// round 5
// speedup vs baseline: 2.3078x; 1.0784x over previous
#include <cuda_runtime.h>
#include <cstdint>

// Problem constants (match reference)
#define BN 64
#define TN 1024
#define DN 256
#define KMAX 128
#define EPSF 1e-3f
#define MMAXT 64                        // lgamma table depth
#define HALF_L2PI 0.91893853320467274f  // 0.5*log(2*pi)
#define LN2F 0.69314718055994531f
#define LOG2EF 1.44269504088896340f
// C1 = -0.5*ln(pi) + ln(1/ln2)  (per-nonzero-obs constant, folded)
#define C1F (-0.20585202294f)

// ---------------------------------------------------------------------------
// Static device scratch
// ---------------------------------------------------------------------------
__device__ int   g_cnt [BN * KMAX];
__device__ int   g_list[BN * KMAX * TN];

// per-dim constants (aligned for vector loads in k_main)
__device__ __align__(16) float g_kappa0[DN];
__device__ __align__(16) float g_a[DN];
__device__ __align__(16) float g_kl2[DN];   // log2e * kappa0 * loc
__device__ __align__(16) float g_cb[DN];    // log2e^2 * (2*b + kappa0*loc^2)
__device__ float g_a0[DN], g_b0[DN];
__device__ float g_lgA0B0[DN], g_lgA0[DN], g_lgB0[DN], g_lgA[DN];

// lgamma difference tables: tab[m][d] = lg(const_d + step*m) - lg(const_d)
__device__ float g_tabA0[MMAXT * DN];
__device__ float g_tabB0[MMAXT * DN];
__device__ float g_tabAB[MMAXT * DN];
__device__ float g_tabAh[MMAXT * DN];

// ---------------------------------------------------------------------------
// Fast lgamma for x > 0: shift to x>=8 (unrolled, predicated), then Stirling.
// ---------------------------------------------------------------------------
__device__ __forceinline__ float fast_lgamma(float x)
{
    float prod = 1.0f;
#pragma unroll
    for (int i = 0; i < 8; i++) {
        if (x < 8.0f) { prod *= x; x += 1.0f; }
    }
    float rx  = __frcp_rn(x);
    float rx2 = rx * rx;
    float ser = rx * (8.33333333e-2f + rx2 * (-2.77777778e-3f + rx2 * 7.93650794e-4f));
    float lx  = __logf(x);
    return fmaf(x - 0.5f, lx, -x) + HALF_L2PI + ser - __logf(prod);
}

// ---------------------------------------------------------------------------
// Kernel 1 (fused prep): blocks [0, MMAXT) build lgamma tables + constants;
// blocks [MMAXT, MMAXT+8) build per-(b,k) time lists (one warp per batch row).
// ---------------------------------------------------------------------------
__global__ void __launch_bounds__(256)
k_prep(const float* __restrict__ loc,
       const float* __restrict__ log_mean_conc,
       const float* __restrict__ log_conc,
       const float* __restrict__ log_scale,
       const float* __restrict__ sparse_prior_logit,
       const int*   __restrict__ z,
       float* __restrict__ out)
{
    if (blockIdx.x < MMAXT) {
        const int m = blockIdx.x;
        const int d = threadIdx.x;
        float kappa0 = expf(fminf(log_mean_conc[d], 12.0f));
        float a      = expf(log_conc[d]);
        float b      = expf(log_scale[d]);
        float a0     = 2.0f * a + 4.0f;                 // nu+1, nu = 2a+3
        float b0     = a0 * expf(sparse_prior_logit[d]);
        float l      = loc[d];

        float lgA0 = fast_lgamma(a0);
        float lgB0 = fast_lgamma(b0);
        float lgAB = fast_lgamma(a0 + b0);
        float lgA  = fast_lgamma(a);

        if (m == 0) {
            g_kappa0[d] = kappa0;
            g_a[d]      = a;
            g_kl2[d]    = LOG2EF * kappa0 * l;
            g_cb[d]     = (LOG2EF * LOG2EF) * fmaf(kappa0 * l, l, 2.0f * b);
            g_a0[d]     = a0;
            g_b0[d]     = b0;
            // exact bases for the (rare) cnt>=MMAXT fallback path
            g_lgA0[d]   = lgammaf(a0);
            g_lgB0[d]   = lgammaf(b0);
            g_lgA0B0[d] = lgammaf(a0 + b0);
            g_lgA[d]    = lgammaf(a);
            if (d < BN) out[d] = 0.0f;                  // out is poisoned
        }

        float fm = (float)m;
        g_tabA0[m * DN + d] = fast_lgamma(a0 + fm)          - lgA0;
        g_tabB0[m * DN + d] = fast_lgamma(b0 + fm)          - lgB0;
        g_tabAB[m * DN + d] = fast_lgamma(a0 + b0 + fm)     - lgAB;
        g_tabAh[m * DN + d] = fast_lgamma(fmaf(0.5f, fm, a)) - lgA;
    } else {
        // ---- list build: one warp per batch row ----
        __shared__ int cs[8][KMAX];
        const int wl   = threadIdx.x >> 5;
        const int lane = threadIdx.x & 31;
        const int b    = (blockIdx.x - MMAXT) * 8 + wl;

        for (int i = threadIdx.x; i < 8 * KMAX; i += blockDim.x)
            ((int*)cs)[i] = 0;
        __syncthreads();

        const int* zr = z + b * TN;
        int* cw = cs[wl];
        const unsigned lmlt = (1u << lane) - 1u;

        for (int t0 = 0; t0 < TN; t0 += 32) {
            int t  = t0 + lane;
            int zv = __ldg(zr + t);                          // coalesced
            unsigned mask = __match_any_sync(0xffffffffu, zv);
            int rank = __popc(mask & lmlt);                  // stable in-chunk rank
            int base = cw[zv];
            __syncwarp();
            g_list[((size_t)(b * KMAX + zv)) * TN + base + rank] = t;
            if (rank == 0)
                cw[zv] = base + __popc(mask);
            __syncwarp();
        }

        for (int k = lane; k < KMAX; k += 32)
            g_cnt[b * KMAX + k] = cw[k];
    }
}

// ---------------------------------------------------------------------------
// Per-observation update, log2 domain. y,s1,s2 in log2 units; acc2 accumulates
// an*lg2(q2) - (an+0.5)*lg2(q2+dy2^2); scale corrections telescope into the
// tail (C1*m1) and one final *ln2.
// ---------------------------------------------------------------------------
__device__ __forceinline__ void obs2(float x, float kap, float a, float kl2, float cb,
                                     float& m1, float& s1, float& s2, float& acc2)
{
    if (x > EPSF) {
        float y   = __log2f(x);
        float kn  = kap + m1;
        float rkn = __frcp_rn(kn);
        float w   = kl2 + s1;
        float mn  = w * rkn;
        float an  = fmaf(0.5f, m1, a);
        float B   = fmaf(-w, mn, s2 + cb);        // = log2e^2 * 2*bn
        float q   = B * (kn + 1.0f) * rkn;        // = log2e^2 * q_nat
        float dy  = y - mn;
        float Lq  = __log2f(q);
        float Lqd = __log2f(fmaf(dy, dy, q));
        acc2 = fmaf(an, Lq - Lqd, acc2);
        acc2 = fmaf(-0.5f, Lqd, acc2);
        s1 += y;
        s2  = fmaf(y, y, s2);
        m1 += 1.0f;
    }
}

// Chain-end telescoped terms for one dim (natural units; s1 in log2 units).
__device__ __forceinline__ float tail2(int d, int cnt, float m1, float s1, float a)
{
    const int M1 = (int)m1;
    const int Z  = cnt - M1;
    float r = fmaf(C1F, m1, -LN2F * s1);   // folded -0.5*ln(pi), log2 scale fix, -Sum y
    if (cnt < MMAXT) {
        r += g_tabA0[M1 * DN + d]      // Sum log(a0+m1)       (nonzero obs)
           + g_tabB0[Z  * DN + d]      // Sum log(b0+n0)       (zero obs)
           + g_tabAh[M1 * DN + d]      // Sum lgamma ratio     (Student-t)
           - g_tabAB[cnt * DN + d];    // -Sum log(a0+b0+ck)
    } else {
        float a0 = g_a0[d], b0 = g_b0[d];
        r += (lgammaf(a0 + m1)             - g_lgA0[d])
           + (lgammaf(b0 + (float)Z)       - g_lgB0[d])
           + (lgammaf(fmaf(0.5f, m1, a))   - g_lgA[d])
           - (lgammaf(a0 + b0 + (float)cnt) - g_lgA0B0[d]);
    }
    return r;
}

// ---------------------------------------------------------------------------
// Kernel 2: main chain evaluation.
// One CTA per (b,k) chain, 128 threads; thread t owns dims 2t, 2t+1 and the
// CTA streams its cluster's X rows as coalesced float2 (full 1KB row / iter).
// ---------------------------------------------------------------------------
__global__ void __launch_bounds__(128)
k_main(const float* __restrict__ X, float* __restrict__ out)
{
    const int id = blockIdx.x;            // chain id = b*KMAX + k
    const int b  = id >> 7;
    const int k  = id & (KMAX - 1);
    const int t  = threadIdx.x;           // dims 2t, 2t+1

    const int cnt = g_cnt[id];
    float accN = 0.0f;

    if (cnt > 0) {
        const float2 K  = ((const float2*)g_kappa0)[t];
        const float2 A  = ((const float2*)g_a)[t];
        const float2 KL = ((const float2*)g_kl2)[t];
        const float2 CB = ((const float2*)g_cb)[t];

        const int* lst = g_list + (size_t)id * TN;
        const float2* Xb = (const float2*)X + ((size_t)b * TN) * (DN / 2) + t;

        float m1a = 0.f, s1a = 0.f, s2a = 0.f;
        float m1b = 0.f, s1b = 0.f, s2b = 0.f;
        float acc2 = 0.f;

        const int cl = cnt - 1;
        int tj = __ldg(lst);
        float2 x = __ldg(Xb + (size_t)tj * (DN / 2));

        for (int j = 0; j < cnt; j++) {
            int jn = min(j + 1, cl);                  // branch-free prefetch clamp
            int tn = __ldg(lst + jn);
            float2 xn = __ldg(Xb + (size_t)tn * (DN / 2));
            obs2(x.x, K.x, A.x, KL.x, CB.x, m1a, s1a, s2a, acc2);
            obs2(x.y, K.y, A.y, KL.y, CB.y, m1b, s1b, s2b, acc2);
            x = xn;
        }

        const int d0 = 2 * t;
        float r = tail2(d0, cnt, m1a, s1a, A.x) + tail2(d0 + 1, cnt, m1b, s1b, A.y);
        accN = fmaf(LN2F, acc2, r);
    }

    // CRP (fully telescoped): Sum_k lgamma(cnt_k) - lgamma(T+1) per batch row
    if (t == 0) {
        if (cnt > 0) accN += fast_lgamma((float)cnt);
        if (k == 0)  accN -= lgammaf((float)(TN + 1));
    }

    // 4-warp reduction
    const int lane = t & 31, wid = t >> 5;
#pragma unroll
    for (int o = 16; o; o >>= 1)
        accN += __shfl_down_sync(0xffffffffu, accN, o);
    __shared__ float wsum[4];
    if (lane == 0) wsum[wid] = accN;
    __syncthreads();
    if (t == 0)
        atomicAdd(&out[b], -(wsum[0] + wsum[1] + wsum[2] + wsum[3]));
}

// ---------------------------------------------------------------------------
// Entry point. Inputs: X, loc, log_mean_conc, log_conc, log_scale,
// sparse_prior_logit, z. Output: float[BN].
// ---------------------------------------------------------------------------
extern "C" void kernel_launch(void* const* d_in, const int* in_sizes, int n_in,
                              void* d_out, int out_size)
{
    const float* X   = (const float*)d_in[0];
    const float* loc = (const float*)d_in[1];
    const float* lmc = (const float*)d_in[2];
    const float* lc  = (const float*)d_in[3];
    const float* ls  = (const float*)d_in[4];
    const float* spl = (const float*)d_in[5];
    const int*   z   = (const int*)d_in[6];
    float* out = (float*)d_out;

    k_prep<<<MMAXT + BN / 8, 256>>>(loc, lmc, lc, ls, spl, z, out);
    k_main<<<BN * KMAX, 128>>>(X, out);
}

// round 6
// speedup vs baseline: 2.6679x; 1.1560x over previous
#include <cuda_runtime.h>
#include <cstdint>

// Problem constants (match reference)
#define BN 64
#define TN 1024
#define DN 256
#define KMAX 128
#define EPSF 1e-3f
#define MMAXT 64                        // lgamma table depth
#define HALF_L2PI 0.91893853320467274f  // 0.5*log(2*pi)
#define LN2F 0.69314718055994531f
#define LOG2EF 1.44269504088896340f
// C1 = ln(log2e) - 0.5*ln(pi)  (per-nonzero-obs constant from log2 scaling)
#define C1F (-0.20585202294f)

// ---------------------------------------------------------------------------
// Static device scratch
// ---------------------------------------------------------------------------
__device__ int   g_cnt [BN * KMAX];
__device__ int   g_list[BN * KMAX * TN];

// per-dim constants (aligned for vector loads in k_main)
__device__ __align__(16) float g_kappa0[DN];
__device__ __align__(16) float g_a[DN];
__device__ __align__(16) float g_kl2[DN];   // log2e * kappa0 * loc
__device__ __align__(16) float g_cb[DN];    // log2e^2 * (2*b + kappa0*loc^2)
__device__ float g_a0[DN], g_b0[DN];
__device__ float g_lgA0B0[DN], g_lgA0[DN], g_lgB0[DN], g_lgA[DN], g_lgK[DN];

// lgamma difference tables: tab[m][d] = telescoped chain-end sums
__device__ float g_tabA0[MMAXT * DN];   // lg(a0+m)-lg(a0)
__device__ float g_tabB0[MMAXT * DN];   // lg(b0+m)-lg(b0)
__device__ float g_tabAB[MMAXT * DN];   // lg(a0+b0+m)-lg(a0+b0)
__device__ float g_tabAh[MMAXT * DN];   // [lg(a+m/2)-lg(a)] + [lg(k0+m)-lg(k0)]

// ---------------------------------------------------------------------------
// Fast lgamma for x > 0: shift to x>=8 (unrolled, predicated), then Stirling.
// ---------------------------------------------------------------------------
__device__ __forceinline__ float fast_lgamma(float x)
{
    float prod = 1.0f;
#pragma unroll
    for (int i = 0; i < 8; i++) {
        if (x < 8.0f) { prod *= x; x += 1.0f; }
    }
    float rx  = __frcp_rn(x);
    float rx2 = rx * rx;
    float ser = rx * (8.33333333e-2f + rx2 * (-2.77777778e-3f + rx2 * 7.93650794e-4f));
    float lx  = __logf(x);
    return fmaf(x - 0.5f, lx, -x) + HALF_L2PI + ser - __logf(prod);
}

// ---------------------------------------------------------------------------
// Kernel 1 (fused prep): blocks [0, MMAXT) build lgamma tables + constants;
// blocks [MMAXT, MMAXT+8) build per-(b,k) time lists (one warp per batch row).
// ---------------------------------------------------------------------------
__global__ void __launch_bounds__(256)
k_prep(const float* __restrict__ loc,
       const float* __restrict__ log_mean_conc,
       const float* __restrict__ log_conc,
       const float* __restrict__ log_scale,
       const float* __restrict__ sparse_prior_logit,
       const int*   __restrict__ z,
       float* __restrict__ out)
{
    if (blockIdx.x < MMAXT) {
        const int m = blockIdx.x;
        const int d = threadIdx.x;
        float kappa0 = expf(fminf(log_mean_conc[d], 12.0f));
        float a      = expf(log_conc[d]);
        float b      = expf(log_scale[d]);
        float a0     = 2.0f * a + 4.0f;                 // nu+1, nu = 2a+3
        float b0     = a0 * expf(sparse_prior_logit[d]);
        float l      = loc[d];

        float lgA0 = fast_lgamma(a0);
        float lgB0 = fast_lgamma(b0);
        float lgAB = fast_lgamma(a0 + b0);
        float lgA  = fast_lgamma(a);
        float lgK  = fast_lgamma(kappa0);

        if (m == 0) {
            g_kappa0[d] = kappa0;
            g_a[d]      = a;
            g_kl2[d]    = LOG2EF * kappa0 * l;
            g_cb[d]     = (LOG2EF * LOG2EF) * fmaf(kappa0 * l, l, 2.0f * b);
            g_a0[d]     = a0;
            g_b0[d]     = b0;
            // exact bases for the (rare) cnt>=MMAXT fallback path
            g_lgA0[d]   = lgammaf(a0);
            g_lgB0[d]   = lgammaf(b0);
            g_lgA0B0[d] = lgammaf(a0 + b0);
            g_lgA[d]    = lgammaf(a);
            g_lgK[d]    = lgammaf(kappa0);
            if (d < BN) out[d] = 0.0f;                  // out is poisoned
        }

        float fm = (float)m;
        g_tabA0[m * DN + d] = fast_lgamma(a0 + fm)          - lgA0;
        g_tabB0[m * DN + d] = fast_lgamma(b0 + fm)          - lgB0;
        g_tabAB[m * DN + d] = fast_lgamma(a0 + b0 + fm)     - lgAB;
        g_tabAh[m * DN + d] = (fast_lgamma(fmaf(0.5f, fm, a)) - lgA)
                            + (fast_lgamma(kappa0 + fm)       - lgK);
    } else {
        // ---- list build: one warp per batch row ----
        __shared__ int cs[8][KMAX];
        const int wl   = threadIdx.x >> 5;
        const int lane = threadIdx.x & 31;
        const int b    = (blockIdx.x - MMAXT) * 8 + wl;

        for (int i = threadIdx.x; i < 8 * KMAX; i += blockDim.x)
            ((int*)cs)[i] = 0;
        __syncthreads();

        const int* zr = z + b * TN;
        int* cw = cs[wl];
        const unsigned lmlt = (1u << lane) - 1u;

        for (int t0 = 0; t0 < TN; t0 += 32) {
            int t  = t0 + lane;
            int zv = __ldg(zr + t);                          // coalesced
            unsigned mask = __match_any_sync(0xffffffffu, zv);
            int rank = __popc(mask & lmlt);                  // stable in-chunk rank
            int base = cw[zv];
            __syncwarp();
            g_list[((size_t)(b * KMAX + zv)) * TN + base + rank] = t;
            if (rank == 0)
                cw[zv] = base + __popc(mask);
            __syncwarp();
        }

        for (int k = lane; k < KMAX; k += 32)
            g_cnt[b * KMAX + k] = cw[k];
    }
}

// ---------------------------------------------------------------------------
// Per-observation update, branchless + division-free (log2 domain).
// State: w = kl2 + Sum(nz*y), s2p = cb + Sum(nz*y^2), kn = kappa0 + m1,
//        an = a + m1/2.  With e = y*kn - w, P = (s2p*kn - w^2)(kn+1),
//        Q = P + e^2:  obs term = an*log2(P) - (an+0.5)*log2(Q)
// (the +log2(kn) residue telescopes into tabAh; scale residue is C1 per obs).
// ---------------------------------------------------------------------------
__device__ __forceinline__ void obs2(float x,
                                     float& w, float& s2p, float& kn, float& an,
                                     float& acc2)
{
    float nzf = (x > EPSF) ? 1.0f : 0.0f;
    float y   = __log2f(fmaxf(x, EPSF));
    float e   = fmaf(y, kn, -w);
    float t1  = fmaf(s2p, kn, -w * w);
    float kn1 = kn + 1.0f;
    float P   = t1 * kn1;
    float Q   = fmaf(e, e, P);
    float LP  = __log2f(P);
    float LQ  = __log2f(Q);
    float th  = fmaf(an, LP - LQ, -0.5f * LQ);
    acc2 = fmaf(nzf, th, acc2);
    float yn = y * nzf;
    w   += yn;
    s2p  = fmaf(yn, y, s2p);
    kn  += nzf;
    an   = fmaf(0.5f, nzf, an);
}

// Chain-end telescoped terms for one dim (natural units; s1 in log2 units).
__device__ __forceinline__ float tail2(int d, int cnt, float m1, float s1,
                                       float a, float kap)
{
    const int M1 = (int)m1;
    const int Z  = cnt - M1;
    float r = fmaf(C1F, m1, -LN2F * s1);   // folded -0.5*ln(pi), scale fix, -Sum y
    if (cnt < MMAXT) {
        r += g_tabA0[M1 * DN + d]      // Sum log(a0+m1)          (nonzero obs)
           + g_tabB0[Z  * DN + d]      // Sum log(b0+n0)          (zero obs)
           + g_tabAh[M1 * DN + d]      // lgamma ratios (Student-t + Sum log kn)
           - g_tabAB[cnt * DN + d];    // -Sum log(a0+b0+ck)
    } else {
        float a0 = g_a0[d], b0 = g_b0[d];
        r += (lgammaf(a0 + m1)             - g_lgA0[d])
           + (lgammaf(b0 + (float)Z)       - g_lgB0[d])
           + (lgammaf(fmaf(0.5f, m1, a))   - g_lgA[d])
           + (lgammaf(kap + m1)            - g_lgK[d])
           - (lgammaf(a0 + b0 + (float)cnt) - g_lgA0B0[d]);
    }
    return r;
}

// ---------------------------------------------------------------------------
// Kernel 2: main chain evaluation.
// One CTA per (b,k) chain, 128 threads; thread t owns dims 2t, 2t+1 and the
// CTA streams its cluster's X rows as coalesced float2 (full 1KB row / iter).
// ---------------------------------------------------------------------------
__global__ void __launch_bounds__(128)
k_main(const float* __restrict__ X, float* __restrict__ out)
{
    const int id = blockIdx.x;            // chain id = b*KMAX + k
    const int b  = id >> 7;
    const int k  = id & (KMAX - 1);
    const int t  = threadIdx.x;           // dims 2t, 2t+1

    const int cnt = g_cnt[id];
    float accN = 0.0f;

    if (cnt > 0) {
        const float2 K  = ((const float2*)g_kappa0)[t];
        const float2 A  = ((const float2*)g_a)[t];
        const float2 KL = ((const float2*)g_kl2)[t];
        const float2 CB = ((const float2*)g_cb)[t];

        const int* lst = g_list + (size_t)id * TN;
        const float2* Xb = (const float2*)X + ((size_t)b * TN) * (DN / 2) + t;

        float wa = KL.x, s2a = CB.x, kna = K.x, ana = A.x;
        float wb = KL.y, s2b = CB.y, knb = K.y, anb = A.y;
        float acc2 = 0.f;

        const int cl = cnt - 1;
        int tj = __ldg(lst);
        float2 x = __ldg(Xb + (size_t)tj * (DN / 2));

        for (int j = 0; j < cnt; j++) {
            int jn = min(j + 1, cl);                  // branch-free prefetch clamp
            int tn = __ldg(lst + jn);
            float2 xn = __ldg(Xb + (size_t)tn * (DN / 2));
            obs2(x.x, wa, s2a, kna, ana, acc2);
            obs2(x.y, wb, s2b, knb, anb, acc2);
            x = xn;
        }

        const int d0 = 2 * t;
        float m1a = rintf(kna - K.x), s1a = wa - KL.x;
        float m1b = rintf(knb - K.y), s1b = wb - KL.y;
        float r = tail2(d0,     cnt, m1a, s1a, A.x, K.x)
                + tail2(d0 + 1, cnt, m1b, s1b, A.y, K.y);
        accN = fmaf(LN2F, acc2, r);
    }

    // CRP (fully telescoped): Sum_k lgamma(cnt_k) - lgamma(T+1) per batch row
    if (t == 0) {
        if (cnt > 0) accN += fast_lgamma((float)cnt);
        if (k == 0)  accN -= lgammaf((float)(TN + 1));
    }

    // 4-warp reduction
    const int lane = t & 31, wid = t >> 5;
#pragma unroll
    for (int o = 16; o; o >>= 1)
        accN += __shfl_down_sync(0xffffffffu, accN, o);
    __shared__ float wsum[4];
    if (lane == 0) wsum[wid] = accN;
    __syncthreads();
    if (t == 0)
        atomicAdd(&out[b], -(wsum[0] + wsum[1] + wsum[2] + wsum[3]));
}

// ---------------------------------------------------------------------------
// Entry point. Inputs: X, loc, log_mean_conc, log_conc, log_scale,
// sparse_prior_logit, z. Output: float[BN].
// ---------------------------------------------------------------------------
extern "C" void kernel_launch(void* const* d_in, const int* in_sizes, int n_in,
                              void* d_out, int out_size)
{
    const float* X   = (const float*)d_in[0];
    const float* loc = (const float*)d_in[1];
    const float* lmc = (const float*)d_in[2];
    const float* lc  = (const float*)d_in[3];
    const float* ls  = (const float*)d_in[4];
    const float* spl = (const float*)d_in[5];
    const int*   z   = (const int*)d_in[6];
    float* out = (float*)d_out;

    k_prep<<<MMAXT + BN / 8, 256>>>(loc, lmc, lc, ls, spl, z, out);
    k_main<<<BN * KMAX, 128>>>(X, out);
}